// round 2
// baseline (speedup 1.0000x reference)
#include <cuda_runtime.h>

// Gumbel-Sinkhorn, multiplicative form.
//   E = exp((gamma + noise) * 5)            (once)
//   repeat niters: r_i = 1/sum_j E_ij c_j ;  c_j = 1/sum_i E_ij r_i
//   out_ij = E_ij * r_i * c_j
//
// One CTA (128 threads) per matrix. Thread t holds row t of E in registers
// (row pass is pure FFMA). E also in smem with stride 132 floats so the
// column pass (Es[i*132 + tid]) is bank-conflict-free: bank = (4i + tid) % 32.

#define NN 128
#define STRIDE 132           // 132 floats = 528 B = 33*16 B (float4-aligned rows)
#define TEMP_INV 5.0f

__global__ __launch_bounds__(128) void sinkhorn_kernel(
    const float* __restrict__ gamma,
    const float* __restrict__ noise,
    const int*   __restrict__ niters_p,
    float*       __restrict__ out)
{
    extern __shared__ float smem[];
    float* Es  = smem;                    // NN * STRIDE
    float* r_s = smem + NN * STRIDE;      // NN
    float* c_s = r_s + NN;                // NN

    const int tid = threadIdx.x;
    const long long base = (long long)blockIdx.x * (NN * NN);
    const int niters = *niters_p;

    // ---- Prologue: E = exp((gamma + noise) * 5), coalesced float4 ----
    const float4* g4 = reinterpret_cast<const float4*>(gamma);
    const float4* n4 = reinterpret_cast<const float4*>(noise + base);
    #pragma unroll
    for (int k = 0; k < 32; ++k) {
        int v  = k * 128 + tid;           // float4 index 0..4095
        int i  = v >> 5;                  // row (each warp writes one full row)
        int j4 = (v & 31) * 4;            // col
        float4 g = g4[v];
        float4 u = n4[v];
        float4 e;
        e.x = __expf((g.x + u.x) * TEMP_INV);
        e.y = __expf((g.y + u.y) * TEMP_INV);
        e.z = __expf((g.z + u.z) * TEMP_INV);
        e.w = __expf((g.w + u.w) * TEMP_INV);
        *reinterpret_cast<float4*>(&Es[i * STRIDE + j4]) = e;
    }
    c_s[tid] = 1.0f;
    __syncthreads();

    // ---- Register row cache: thread t owns row t ----
    float rowE[NN];
    #pragma unroll
    for (int m = 0; m < 32; ++m) {
        float4 e = *reinterpret_cast<const float4*>(&Es[tid * STRIDE + 4 * m]);
        rowE[4 * m + 0] = e.x;
        rowE[4 * m + 1] = e.y;
        rowE[4 * m + 2] = e.z;
        rowE[4 * m + 3] = e.w;
    }

    // ---- Sinkhorn iterations ----
    for (int it = 0; it < niters; ++it) {
        // Row pass (registers): S_t = sum_j rowE[j] * c[j]
        float a0 = 0.f, a1 = 0.f, a2 = 0.f, a3 = 0.f;
        #pragma unroll
        for (int j = 0; j < NN; j += 4) {
            a0 += rowE[j + 0] * c_s[j + 0];
            a1 += rowE[j + 1] * c_s[j + 1];
            a2 += rowE[j + 2] * c_s[j + 2];
            a3 += rowE[j + 3] * c_s[j + 3];
        }
        float S = (a0 + a1) + (a2 + a3);
        r_s[tid] = __fdividef(1.0f, S);
        __syncthreads();

        // Col pass (smem, conflict-free): T_j = sum_i Es[i][j] * r[i]
        float b0 = 0.f, b1 = 0.f, b2 = 0.f, b3 = 0.f;
        #pragma unroll
        for (int i = 0; i < NN; i += 4) {
            b0 += Es[(i + 0) * STRIDE + tid] * r_s[i + 0];
            b1 += Es[(i + 1) * STRIDE + tid] * r_s[i + 1];
            b2 += Es[(i + 2) * STRIDE + tid] * r_s[i + 2];
            b3 += Es[(i + 3) * STRIDE + tid] * r_s[i + 3];
        }
        float T = (b0 + b1) + (b2 + b3);
        c_s[tid] = __fdividef(1.0f, T);
        __syncthreads();
    }

    // ---- Epilogue: out = E * r * c, coalesced float4 ----
    float4* o4 = reinterpret_cast<float4*>(out + base);
    #pragma unroll
    for (int k = 0; k < 32; ++k) {
        int v  = k * 128 + tid;
        int i  = v >> 5;
        int j4 = (v & 31) * 4;
        float ri = r_s[i];
        float4 e = *reinterpret_cast<const float4*>(&Es[i * STRIDE + j4]);
        float4 o;
        o.x = e.x * ri * c_s[j4 + 0];
        o.y = e.y * ri * c_s[j4 + 1];
        o.z = e.z * ri * c_s[j4 + 2];
        o.w = e.w * ri * c_s[j4 + 3];
        o4[v] = o;
    }
}

extern "C" void kernel_launch(void* const* d_in, const int* in_sizes, int n_in,
                              void* d_out, int out_size)
{
    // Identify inputs by element count (robust to ordering):
    //   gamma: 128*128, noise: B*128*128 (largest), niters: 1
    int gi = -1, ni = -1, si = -1;
    long long best = -1;
    for (int k = 0; k < n_in; ++k) {
        if (in_sizes[k] == 1) { si = k; }
        else if (in_sizes[k] == NN * NN && gi < 0) { gi = k; }
        if ((long long)in_sizes[k] > best) { best = in_sizes[k]; ni = k; }
    }
    if (ni == gi) { // degenerate B==1 case safety
        for (int k = 0; k < n_in; ++k)
            if (k != gi && in_sizes[k] == NN * NN) { ni = k; break; }
    }

    const float* gamma = (const float*)d_in[gi];
    const float* noise = (const float*)d_in[ni];
    const int*   nit   = (const int*)d_in[si];
    float* out = (float*)d_out;

    int B = in_sizes[ni] / (NN * NN);

    const int smem_bytes = (NN * STRIDE + 2 * NN) * (int)sizeof(float);
    static bool attr_set = false;
    if (!attr_set) {
        cudaFuncSetAttribute(sinkhorn_kernel,
                             cudaFuncAttributeMaxDynamicSharedMemorySize,
                             smem_bytes);
        attr_set = true;
    }

    sinkhorn_kernel<<<B, 128, smem_bytes>>>(gamma, noise, nit, out);
}